// round 15
// baseline (speedup 1.0000x reference)
#include <cuda_runtime.h>
#include <math.h>
#include <stdint.h>

#define NN 8192
#define KK 32
#define NT 64                       // 8192/128 row-tiles
#define NOFF (NT*(NT-1)/2)          // 2016 upper 128x128 tiles
#define NOFF2 (2*NOFF)              // 4032 off half-tiles (128x64)
#define NDIAG2 (2*NT)               // 128 diag half-tiles
#define NBLK (NOFF2 + NDIAG2)       // 4160 blocks
#define PB 128                      // prep blocks

typedef unsigned long long u64;

#define FMA2(d,a,b,c) asm("fma.rn.f32x2 %0, %1, %2, %3;" : "=l"(d) : "l"(a), "l"(b), "l"(c))
#define PK2(d,lo,hi)  asm("mov.b64 %0, {%1, %2};" : "=l"(d) : "f"(lo), "f"(hi))
#define UPK2(lo,hi,s) asm("mov.b64 {%0, %1}, %2;" : "=f"(lo), "=f"(hi) : "l"(s))
#define CPA16(dst,src) asm volatile("cp.async.cg.shared.global [%0], [%1], 16;" :: "r"(dst), "l"(src))

// ---- scratch ----
__device__ float  d_Wpart[PB*KK*KK];
__device__ float  d_Spart[PB*KK];
__device__ float  d_M [KK*KK];
__device__ float  d_Ya  [KK*NN];
__device__ float  d_bv  [NN];
__device__ double d_partSP[NBLK];
__device__ double d_partTA[NBLK];
__device__ unsigned d_ctrP = 0;
__device__ unsigned d_ctrK = 0;

// ---------- prep: softmax(X) + exp(C) + partial W,S; last block builds M ----------
__global__ void k_prep(const float* __restrict__ X, const float* __restrict__ C) {
    __shared__ float xs[KK][66];
    __shared__ float ec[KK][66];
    __shared__ float inv[64];
    __shared__ float Es[KK*KK];
    __shared__ float Ssm[KK];
    __shared__ unsigned isLast;
    int blk = blockIdx.x, tid = threadIdx.x;
    int base = blk * 64;

#pragma unroll
    for (int c = 0; c < 8; c++) {
        int idx = c*256 + tid;
        int p = idx >> 6, col = idx & 63;
        xs[p][col] = __expf(X[p*NN + base + col]);
    }
#pragma unroll
    for (int c = 0; c < 8; c++) {
        int idx = c*256 + tid;
        int row = idx >> 5, k = idx & 31;
        ec[k][row] = __expf(C[(u64)(base + row)*KK + k]);
    }
    __syncthreads();

    if (tid < 64) {
        float s = 0.f;
#pragma unroll
        for (int p = 0; p < KK; p++) s += xs[p][tid];
        inv[tid] = 1.f / s;
    } else if (tid < 96) {
        int k = tid - 64;
        float s = 0.f;
#pragma unroll 8
        for (int r = 0; r < 64; r++) s += ec[k][r];
        d_Spart[blk*32 + k] = s;
    }
    __syncthreads();

#pragma unroll
    for (int c = 0; c < 8; c++) {
        int idx = c*256 + tid;
        int p = idx >> 6, col = idx & 63;
        xs[p][col] *= inv[col];
    }
    __syncthreads();

    int p = tid >> 3, k0 = (tid & 7) * 4;
    float a0 = 0.f, a1 = 0.f, a2 = 0.f, a3 = 0.f;
#pragma unroll 8
    for (int i = 0; i < 64; i++) {
        float xv = xs[p][i];
        a0 += xv * ec[k0+0][i];
        a1 += xv * ec[k0+1][i];
        a2 += xv * ec[k0+2][i];
        a3 += xv * ec[k0+3][i];
    }
    float* out = &d_Wpart[blk*1024 + p*32 + k0];
    out[0] = a0; out[1] = a1; out[2] = a2; out[3] = a3;

    // ---- last-block reduce -> M (deterministic; runs once) ----
    __threadfence();
    if (tid == 0) isLast = (atomicAdd(&d_ctrP, 1) == PB - 1) ? 1u : 0u;
    __syncthreads();
    if (!isLast) return;

    float4 w = make_float4(0.f, 0.f, 0.f, 0.f);
#pragma unroll 8
    for (int b = 0; b < PB; b++) {
        float4 v = __ldcg((const float4*)&d_Wpart[b*1024 + tid*4]);
        w.x += v.x; w.y += v.y; w.z += v.z; w.w += v.w;
    }
    if (tid < 32) {
        float s = 0.f;
#pragma unroll 8
        for (int b = 0; b < PB; b++) s += __ldcg(&d_Spart[b*32 + tid]);
        Ssm[tid] = s;
    }
    __syncthreads();
    {
        int e = tid*4;
        Es[e+0] = w.x / Ssm[(e+0) & 31];
        Es[e+1] = w.y / Ssm[(e+1) & 31];
        Es[e+2] = w.z / Ssm[(e+2) & 31];
        Es[e+3] = w.w / Ssm[(e+3) & 31];
    }
    __syncthreads();
#pragma unroll
    for (int c = 0; c < 4; c++) {
        int e = tid*4 + c;
        int pp = e >> 5, q = e & 31;
        float s = 0.f;
#pragma unroll
        for (int r = 0; r < KK; r++) s += Es[r*KK + pp] * Es[r*KK + q];
        d_M[e] = s;
    }
    if (tid == 0) d_ctrP = 0;    // reset for next graph replay
}

// ---------- Ya = 2a*M*X, b = beta - a*q (32 cols/block, 256 blocks) ----------
__global__ void k_ya(const float* __restrict__ X, const float* __restrict__ beta,
                     const float* __restrict__ a_p) {
    __shared__ __align__(16) float Ms[KK][KK];
    __shared__ float Xw[KK][33];
    __shared__ float qsm[8][32];
    int tid = threadIdx.x;
    int cbase = blockIdx.x * 32;

#pragma unroll
    for (int c = 0; c < 4; c++) {
        int idx = c*256 + tid;
        int q = idx >> 5, col = idx & 31;
        Xw[q][col] = X[q*NN + cbase + col];
    }
#pragma unroll
    for (int c = 0; c < 4; c++) {
        int idx = c*256 + tid;
        Ms[idx >> 5][idx & 31] = d_M[idx];
    }
    __syncthreads();

    int col = tid & 31, pg = tid >> 5;
    float a = a_p[0];
    float twoa = 2.f * a;
    float xv[KK];
#pragma unroll
    for (int q = 0; q < KK; q++) xv[q] = Xw[q][col];

    int i = cbase + col;
    float qp = 0.f;
#pragma unroll
    for (int pp = 0; pp < 4; pp++) {
        int p = pg*4 + pp;
        const float4* mrow = (const float4*)&Ms[p][0];
        float tp = 0.f;
#pragma unroll
        for (int q4 = 0; q4 < 8; q4++) {
            float4 m = mrow[q4];
            tp += m.x * xv[q4*4+0] + m.y * xv[q4*4+1]
                + m.z * xv[q4*4+2] + m.w * xv[q4*4+3];
        }
        d_Ya[p*NN + i] = twoa * tp;
        qp += xv[p] * tp;
    }
    qsm[pg][col] = qp;
    __syncthreads();
    if (pg == 0) {
        float qf = 0.f;
#pragma unroll
        for (int g = 0; g < 8; g++) qf += qsm[g][col];
        d_bv[i] = beta[i] - a * qf;
    }
}

__device__ __forceinline__ float softplusf(float x) {
    return fmaxf(x, 0.f) + __logf(1.f + __expf(-fabsf(x)));
}

// ---------- unified half-tile kernel (128 rows x 64 cols), 4160 blocks ----------
#define SM_XT2   0
#define SM_YT2   16384
#define SM_ASM2  24576
#define SM_BI2   57344
#define SM_BJ2   57856
#define SM_RED2  58112
#define OFF_SMEM2 58304          // red area enlarged for the final tail (24 doubles)

__global__ void __launch_bounds__(256, 3)
k_pairs(const float* __restrict__ X, const float* __restrict__ A,
        float* __restrict__ out) {
    extern __shared__ char sm[];
    float (*Xt)[128] = (float(*)[128])(sm + SM_XT2);
    float (*Yt)[64]  = (float(*)[64]) (sm + SM_YT2);
    float (*Asm)[64] = (float(*)[64]) (sm + SM_ASM2);
    float* bI  = (float*)(sm + SM_BI2);
    float* bJ  = (float*)(sm + SM_BJ2);
    float* red = (float*)(sm + SM_RED2);
    __shared__ unsigned isLast;

    int bid = blockIdx.x, tid = threadIdx.x;
    int iBase, jBase, h;
    bool isDiag;
    if (bid < NOFF2) {
        int t = bid >> 1; h = bid & 1;
        int I = 0;
        { int rem = t, rl = NT - 1; while (rem >= rl) { rem -= rl; rl--; I++; } t = rem; }
        int J = I + 1 + t;
        iBase = I * 128; jBase = J * 128 + h * 64;
        isDiag = false;
    } else {
        int d = bid - NOFF2;
        int I = d >> 1; h = d & 1;
        iBase = I * 128; jBase = I * 128 + h * 64;
        isDiag = true;
    }

    // ---- stage dir A half-block (128x64) via cp.async ----
    {
        uint32_t abase = (uint32_t)__cvta_generic_to_shared(&Asm[0][0]);
#pragma unroll
        for (int c = 0; c < 8; c++) {
            int idx = c*256 + tid;
            int row = idx >> 4, c16 = idx & 15;
            CPA16(abase + row*256 + c16*16,
                  &A[(u64)(iBase + row)*NN + jBase + c16*4]);
        }
        asm volatile("cp.async.commit_group;");
    }

    // ---- stage X (128 cols) / Ya (64 cols) + biases ----
#pragma unroll
    for (int c = 0; c < 4; c++) {
        int idx = c*256 + tid;
        int p = idx >> 5, ii4 = idx & 31;
        *(float4*)&Xt[p][ii4*4] = *(const float4*)&X[p*NN + iBase + ii4*4];
    }
#pragma unroll
    for (int c = 0; c < 2; c++) {
        int idx = c*256 + tid;
        int p = idx >> 4, ii4 = idx & 15;
        *(float4*)&Yt[p][ii4*4] = *(const float4*)&d_Ya[p*NN + jBase + ii4*4];
    }
    if (tid < 128) bI[tid] = d_bv[iBase + tid];
    else if (tid < 192) bJ[tid - 128] = d_bv[jBase + tid - 128];
    __syncthreads();

    int tx = tid & 15, ty = tid >> 4;
    float bIr[8], bJc[4];
#pragma unroll
    for (int r = 0; r < 8; r++) bIr[r] = bI[ty*8 + r];
#pragma unroll
    for (int c = 0; c < 4; c++) bJc[c] = bJ[tx*4 + c];

    u64 acc2[8][2];
#pragma unroll
    for (int r = 0; r < 8; r++)
#pragma unroll
        for (int cp = 0; cp < 2; cp++)
            PK2(acc2[r][cp], bIr[r] + bJc[2*cp], bIr[r] + bJc[2*cp + 1]);

    // ---- FFMA2 mainloop ----
#pragma unroll
    for (int k = 0; k < KK; k++) {
        float4 xa = *(float4*)&Xt[k][ty*8];
        float4 xb = *(float4*)&Xt[k][ty*8 + 4];
        const u64* yp = (const u64*)&Yt[k][tx*4];
        u64 y2[2] = {yp[0], yp[1]};
        float xf[8] = {xa.x, xa.y, xa.z, xa.w, xb.x, xb.y, xb.z, xb.w};
#pragma unroll
        for (int r = 0; r < 8; r++) {
            u64 xx;
            PK2(xx, xf[r], xf[r]);
            FMA2(acc2[r][0], xx, y2[0], acc2[r][0]);
            FMA2(acc2[r][1], xx, y2[1], acc2[r][1]);
        }
    }
    // theta in acc2

    asm volatile("cp.async.wait_group 0;");
    __syncthreads();

    float sSP = 0.f, sTA = 0.f;
    u64 sTA2; PK2(sTA2, 0.f, 0.f);

    if (!isDiag) {
        // ---- transposed A block (LDG burst; R12-proven order) ----
#pragma unroll
        for (int c = 0; c < 4; c++) {
            int gj = jBase + tx*4 + c;
            float4 b0 = __ldcs((const float4*)&A[(u64)gj*NN + iBase + ty*8]);
            float4 b1 = __ldcs((const float4*)&A[(u64)gj*NN + iBase + ty*8 + 4]);
            float atv[8] = {b0.x, b0.y, b0.z, b0.w, b1.x, b1.y, b1.z, b1.w};
            int cp = c >> 1;
#pragma unroll
            for (int r = 0; r < 8; r++) {
                float t0, t1;
                UPK2(t0, t1, acc2[r][cp]);
                sTA += ((c & 1) ? t1 : t0) * atv[r];
            }
        }

        // ---- dir A half-block from smem + softplus (interleaved) ----
#pragma unroll
        for (int r = 0; r < 8; r++) {
            int row = ty*8 + r;
            float4 a0 = *(const float4*)&Asm[row][tx*4];
            u64 a2[2];
            PK2(a2[0], a0.x, a0.y); PK2(a2[1], a0.z, a0.w);
#pragma unroll
            for (int cp = 0; cp < 2; cp++) {
                float t0, t1;
                UPK2(t0, t1, acc2[r][cp]);
                sSP += softplusf(t0) + softplusf(t1);
                FMA2(sTA2, acc2[r][cp], a2[cp], sTA2);
            }
        }
        sSP *= 2.f;
    } else {
        // ---- diag half: dir-sum only; softplus masked strict-upper (x2) ----
        int colBase = h*64 + tx*4;
#pragma unroll
        for (int r = 0; r < 8; r++) {
            int row = ty*8 + r;
            float4 a0 = *(const float4*)&Asm[row][tx*4];
            u64 a2[2];
            PK2(a2[0], a0.x, a0.y); PK2(a2[1], a0.z, a0.w);
#pragma unroll
            for (int cp = 0; cp < 2; cp++) {
                float t0, t1;
                UPK2(t0, t1, acc2[r][cp]);
                FMA2(sTA2, acc2[r][cp], a2[cp], sTA2);
                if (row < colBase + 2*cp)     sSP += 2.f * softplusf(t0);
                if (row < colBase + 2*cp + 1) sSP += 2.f * softplusf(t1);
            }
        }
    }
    {
        float t0, t1;
        UPK2(t0, t1, sTA2);
        sTA += t0 + t1;
    }

    // ---- deterministic block reduction ----
#pragma unroll
    for (int o = 16; o > 0; o >>= 1) {
        sSP += __shfl_xor_sync(0xffffffffu, sSP, o);
        sTA += __shfl_xor_sync(0xffffffffu, sTA, o);
    }
    int wid = tid >> 5, lane = tid & 31;
    if (lane == 0) { red[wid] = sSP; red[8 + wid] = sTA; }
    __syncthreads();
    if (tid == 0) {
        float s1 = 0.f, s2 = 0.f;
#pragma unroll
        for (int w = 0; w < 8; w++) { s1 += red[w]; s2 += red[8 + w]; }
        d_partSP[bid] = (double)s1;
        d_partTA[bid] = (double)s2;
    }

    // ---- last-block final reduction (deterministic) ----
    __threadfence();
    if (tid == 0) isLast = (atomicAdd(&d_ctrK, 1) == NBLK - 1) ? 1u : 0u;
    __syncthreads();
    if (!isLast) return;

    double s1 = 0.0, s2 = 0.0;
    for (int i = tid; i < NBLK; i += 256) {
        s1 += __ldcg(&d_partSP[i]);
        s2 += __ldcg(&d_partTA[i]);
    }
    // warp reduce doubles deterministically via smem tree
    double* rS = (double*)(sm);           // reuse Xt area (no longer needed)
    double* rT = rS + 256;
    rS[tid] = s1; rT[tid] = s2;
    __syncthreads();
    for (int s = 128; s > 0; s >>= 1) {
        if (tid < s) { rS[tid] += rS[tid+s]; rT[tid] += rT[tid+s]; }
        __syncthreads();
    }
    if (tid == 0) {
        out[0] = (float)(0.5 * rT[0] - 0.5 * rS[0]);
        d_ctrK = 0;   // reset for next graph replay
    }
}

extern "C" void kernel_launch(void* const* d_in, const int* in_sizes, int n_in,
                              void* d_out, int out_size) {
    const float* A    = (const float*)d_in[0];
    const float* beta = (const float*)d_in[1];
    const float* a    = (const float*)d_in[2];
    const float* X    = (const float*)d_in[3];
    const float* C    = (const float*)d_in[4];
    float* out = (float*)d_out;

    cudaFuncSetAttribute(k_pairs, cudaFuncAttributeMaxDynamicSharedMemorySize, OFF_SMEM2);

    k_prep<<<PB, 256>>>(X, C);                       // 1 (+M tail)
    k_ya<<<NN/32, 256>>>(X, beta, a);                // 2
    k_pairs<<<NBLK, 256, OFF_SMEM2>>>(X, A, out);    // 3 (+final tail)
}

// round 16
// speedup vs baseline: 1.0414x; 1.0414x over previous
#include <cuda_runtime.h>
#include <math.h>
#include <stdint.h>

#define NN 8192
#define KK 32
#define NT 64                       // 8192/128 row-tiles
#define NOFF (NT*(NT-1)/2)          // 2016 upper 128x128 tiles
#define NOFF2 (2*NOFF)              // 4032 off half-tiles (128x64)
#define NDIAG2 (2*NT)               // 128 diag half-tiles
#define NBLK (NOFF2 + NDIAG2)       // 4160 blocks
#define PB 128                      // prep blocks

typedef unsigned long long u64;

#define FMA2(d,a,b,c) asm("fma.rn.f32x2 %0, %1, %2, %3;" : "=l"(d) : "l"(a), "l"(b), "l"(c))
#define PK2(d,lo,hi)  asm("mov.b64 %0, {%1, %2};" : "=l"(d) : "f"(lo), "f"(hi))
#define UPK2(lo,hi,s) asm("mov.b64 {%0, %1}, %2;" : "=f"(lo), "=f"(hi) : "l"(s))
#define CPA16(dst,src) asm volatile("cp.async.cg.shared.global [%0], [%1], 16;" :: "r"(dst), "l"(src))

// ---- scratch ----
__device__ float  d_Wpart[PB*KK*KK];
__device__ float  d_Spart[PB*KK];
__device__ float  d_M [KK*KK];
__device__ float  d_Ya  [KK*NN];
__device__ float  d_bv  [NN];
__device__ double d_partSP[NBLK];
__device__ double d_partTA[NBLK];

// ---------- prep: softmax(X) + exp(C) + partial W,S ; 512 threads for latency hiding ----------
__global__ void k_prep(const float* __restrict__ X, const float* __restrict__ C) {
    __shared__ float xs[KK][66];
    __shared__ float ec[KK][66];
    __shared__ float inv[64];
    int blk = blockIdx.x, tid = threadIdx.x;     // 512 threads
    int base = blk * 64;

    // stage exp(X): 2048 elements, 4 per thread, coalesced 64-wide rows
#pragma unroll
    for (int c = 0; c < 4; c++) {
        int idx = c*512 + tid;
        int p = idx >> 6, col = idx & 63;
        xs[p][col] = __expf(X[p*NN + base + col]);
    }
    // stage exp(C): 64 rows x 32 floats = 512 float4 chunks, one per thread
    {
        int row = tid >> 3, q4 = tid & 7;        // 8 float4 per row
        float4 v = *(const float4*)&C[(u64)(base + row)*KK + q4*4];
        ec[q4*4+0][row] = __expf(v.x);
        ec[q4*4+1][row] = __expf(v.y);
        ec[q4*4+2][row] = __expf(v.z);
        ec[q4*4+3][row] = __expf(v.w);
    }
    __syncthreads();

    if (tid < 64) {
        float s = 0.f;
#pragma unroll
        for (int p = 0; p < KK; p++) s += xs[p][tid];
        inv[tid] = 1.f / s;
    } else if (tid < 96) {
        int k = tid - 64;
        float s = 0.f;
#pragma unroll 8
        for (int r = 0; r < 64; r++) s += ec[k][r];
        d_Spart[blk*32 + k] = s;
    }
    __syncthreads();

    // normalize xs in place (4 per thread)
#pragma unroll
    for (int c = 0; c < 4; c++) {
        int idx = c*512 + tid;
        int p = idx >> 6, col = idx & 63;
        xs[p][col] *= inv[col];
    }
    __syncthreads();

    // partial W = Xs_chunk @ expC_chunk (32x32x64); 2 outputs per thread
    int p = tid >> 4, k0 = (tid & 15) * 2;
    float a0 = 0.f, a1 = 0.f;
#pragma unroll 8
    for (int i = 0; i < 64; i++) {
        float xv = xs[p][i];
        a0 += xv * ec[k0+0][i];
        a1 += xv * ec[k0+1][i];
    }
    float* out = &d_Wpart[blk*1024 + p*32 + k0];
    out[0] = a0; out[1] = a1;
}

// ---------- reduce partials (float4, high MLP), E = W/S, M = E^T E ----------
__global__ void k_wredM() {
    __shared__ float Es[KK*KK];
    __shared__ float Ssm[KK];
    int tid = threadIdx.x;

    float4 w = make_float4(0.f, 0.f, 0.f, 0.f);
#pragma unroll 8
    for (int b = 0; b < PB; b++) {
        float4 v = *(const float4*)&d_Wpart[b*1024 + tid*4];
        w.x += v.x; w.y += v.y; w.z += v.z; w.w += v.w;
    }
    if (tid < 32) {
        float s = 0.f;
#pragma unroll 8
        for (int b = 0; b < PB; b++) s += d_Spart[b*32 + tid];
        Ssm[tid] = s;
    }
    __syncthreads();
    {
        int e = tid*4;
        Es[e+0] = w.x / Ssm[(e+0) & 31];
        Es[e+1] = w.y / Ssm[(e+1) & 31];
        Es[e+2] = w.z / Ssm[(e+2) & 31];
        Es[e+3] = w.w / Ssm[(e+3) & 31];
    }
    __syncthreads();
#pragma unroll
    for (int c = 0; c < 4; c++) {
        int e = tid*4 + c;
        int p = e >> 5, q = e & 31;
        float s = 0.f;
#pragma unroll
        for (int r = 0; r < KK; r++) s += Es[r*KK + p] * Es[r*KK + q];
        d_M[e] = s;
    }
}

// ---------- Ya = 2a*M*X, b = beta - a*q (32 cols/block, 256 blocks) ----------
__global__ void k_ya(const float* __restrict__ X, const float* __restrict__ beta,
                     const float* __restrict__ a_p) {
    __shared__ __align__(16) float Ms[KK][KK];
    __shared__ float Xw[KK][33];
    __shared__ float qsm[8][32];
    int tid = threadIdx.x;
    int cbase = blockIdx.x * 32;

#pragma unroll
    for (int c = 0; c < 4; c++) {
        int idx = c*256 + tid;
        int q = idx >> 5, col = idx & 31;
        Xw[q][col] = X[q*NN + cbase + col];
    }
#pragma unroll
    for (int c = 0; c < 4; c++) {
        int idx = c*256 + tid;
        Ms[idx >> 5][idx & 31] = d_M[idx];
    }
    __syncthreads();

    int col = tid & 31, pg = tid >> 5;
    float a = a_p[0];
    float twoa = 2.f * a;
    float xv[KK];
#pragma unroll
    for (int q = 0; q < KK; q++) xv[q] = Xw[q][col];

    int i = cbase + col;
    float qp = 0.f;
#pragma unroll
    for (int pp = 0; pp < 4; pp++) {
        int p = pg*4 + pp;
        const float4* mrow = (const float4*)&Ms[p][0];
        float tp = 0.f;
#pragma unroll
        for (int q4 = 0; q4 < 8; q4++) {
            float4 m = mrow[q4];
            tp += m.x * xv[q4*4+0] + m.y * xv[q4*4+1]
                + m.z * xv[q4*4+2] + m.w * xv[q4*4+3];
        }
        d_Ya[p*NN + i] = twoa * tp;
        qp += xv[p] * tp;
    }
    qsm[pg][col] = qp;
    __syncthreads();
    if (pg == 0) {
        float qf = 0.f;
#pragma unroll
        for (int g = 0; g < 8; g++) qf += qsm[g][col];
        d_bv[i] = beta[i] - a * qf;
    }
}

__device__ __forceinline__ float softplusf(float x) {
    return fmaxf(x, 0.f) + __logf(1.f + __expf(-fabsf(x)));
}

// ---------- unified half-tile kernel (128 rows x 64 cols), 4160 blocks (R14 exact) ----------
#define SM_XT2   0
#define SM_YT2   16384
#define SM_ASM2  24576
#define SM_BI2   57344
#define SM_BJ2   57856
#define SM_RED2  58112
#define OFF_SMEM2 58176

__global__ void __launch_bounds__(256, 3)
k_pairs(const float* __restrict__ X, const float* __restrict__ A) {
    extern __shared__ char sm[];
    float (*Xt)[128] = (float(*)[128])(sm + SM_XT2);
    float (*Yt)[64]  = (float(*)[64]) (sm + SM_YT2);
    float (*Asm)[64] = (float(*)[64]) (sm + SM_ASM2);
    float* bI  = (float*)(sm + SM_BI2);
    float* bJ  = (float*)(sm + SM_BJ2);
    float* red = (float*)(sm + SM_RED2);

    int bid = blockIdx.x, tid = threadIdx.x;
    int iBase, jBase, h;
    bool isDiag;
    if (bid < NOFF2) {
        int t = bid >> 1; h = bid & 1;
        int I = 0;
        { int rem = t, rl = NT - 1; while (rem >= rl) { rem -= rl; rl--; I++; } t = rem; }
        int J = I + 1 + t;
        iBase = I * 128; jBase = J * 128 + h * 64;
        isDiag = false;
    } else {
        int d = bid - NOFF2;
        int I = d >> 1; h = d & 1;
        iBase = I * 128; jBase = I * 128 + h * 64;
        isDiag = true;
    }

    // ---- stage dir A half-block (128x64) via cp.async ----
    {
        uint32_t abase = (uint32_t)__cvta_generic_to_shared(&Asm[0][0]);
#pragma unroll
        for (int c = 0; c < 8; c++) {
            int idx = c*256 + tid;
            int row = idx >> 4, c16 = idx & 15;
            CPA16(abase + row*256 + c16*16,
                  &A[(u64)(iBase + row)*NN + jBase + c16*4]);
        }
        asm volatile("cp.async.commit_group;");
    }

    // ---- stage X (128 cols) / Ya (64 cols) + biases ----
#pragma unroll
    for (int c = 0; c < 4; c++) {
        int idx = c*256 + tid;
        int p = idx >> 5, ii4 = idx & 31;
        *(float4*)&Xt[p][ii4*4] = *(const float4*)&X[p*NN + iBase + ii4*4];
    }
#pragma unroll
    for (int c = 0; c < 2; c++) {
        int idx = c*256 + tid;
        int p = idx >> 4, ii4 = idx & 15;
        *(float4*)&Yt[p][ii4*4] = *(const float4*)&d_Ya[p*NN + jBase + ii4*4];
    }
    if (tid < 128) bI[tid] = d_bv[iBase + tid];
    else if (tid < 192) bJ[tid - 128] = d_bv[jBase + tid - 128];
    __syncthreads();

    int tx = tid & 15, ty = tid >> 4;
    float bIr[8], bJc[4];
#pragma unroll
    for (int r = 0; r < 8; r++) bIr[r] = bI[ty*8 + r];
#pragma unroll
    for (int c = 0; c < 4; c++) bJc[c] = bJ[tx*4 + c];

    u64 acc2[8][2];
#pragma unroll
    for (int r = 0; r < 8; r++)
#pragma unroll
        for (int cp = 0; cp < 2; cp++)
            PK2(acc2[r][cp], bIr[r] + bJc[2*cp], bIr[r] + bJc[2*cp + 1]);

    // ---- FFMA2 mainloop ----
#pragma unroll
    for (int k = 0; k < KK; k++) {
        float4 xa = *(float4*)&Xt[k][ty*8];
        float4 xb = *(float4*)&Xt[k][ty*8 + 4];
        const u64* yp = (const u64*)&Yt[k][tx*4];
        u64 y2[2] = {yp[0], yp[1]};
        float xf[8] = {xa.x, xa.y, xa.z, xa.w, xb.x, xb.y, xb.z, xb.w};
#pragma unroll
        for (int r = 0; r < 8; r++) {
            u64 xx;
            PK2(xx, xf[r], xf[r]);
            FMA2(acc2[r][0], xx, y2[0], acc2[r][0]);
            FMA2(acc2[r][1], xx, y2[1], acc2[r][1]);
        }
    }
    // theta in acc2

    asm volatile("cp.async.wait_group 0;");
    __syncthreads();

    float sSP = 0.f, sTA = 0.f;
    u64 sTA2; PK2(sTA2, 0.f, 0.f);

    if (!isDiag) {
        // ---- transposed A block (LDG burst; R12-proven order) ----
#pragma unroll
        for (int c = 0; c < 4; c++) {
            int gj = jBase + tx*4 + c;
            float4 b0 = __ldcs((const float4*)&A[(u64)gj*NN + iBase + ty*8]);
            float4 b1 = __ldcs((const float4*)&A[(u64)gj*NN + iBase + ty*8 + 4]);
            float atv[8] = {b0.x, b0.y, b0.z, b0.w, b1.x, b1.y, b1.z, b1.w};
            int cp = c >> 1;
#pragma unroll
            for (int r = 0; r < 8; r++) {
                float t0, t1;
                UPK2(t0, t1, acc2[r][cp]);
                sTA += ((c & 1) ? t1 : t0) * atv[r];
            }
        }

        // ---- dir A half-block from smem + softplus (interleaved) ----
#pragma unroll
        for (int r = 0; r < 8; r++) {
            int row = ty*8 + r;
            float4 a0 = *(const float4*)&Asm[row][tx*4];
            u64 a2[2];
            PK2(a2[0], a0.x, a0.y); PK2(a2[1], a0.z, a0.w);
#pragma unroll
            for (int cp = 0; cp < 2; cp++) {
                float t0, t1;
                UPK2(t0, t1, acc2[r][cp]);
                sSP += softplusf(t0) + softplusf(t1);
                FMA2(sTA2, acc2[r][cp], a2[cp], sTA2);
            }
        }
        sSP *= 2.f;
    } else {
        // ---- diag half: dir-sum only; softplus masked strict-upper (x2) ----
        int colBase = h*64 + tx*4;
#pragma unroll
        for (int r = 0; r < 8; r++) {
            int row = ty*8 + r;
            float4 a0 = *(const float4*)&Asm[row][tx*4];
            u64 a2[2];
            PK2(a2[0], a0.x, a0.y); PK2(a2[1], a0.z, a0.w);
#pragma unroll
            for (int cp = 0; cp < 2; cp++) {
                float t0, t1;
                UPK2(t0, t1, acc2[r][cp]);
                FMA2(sTA2, acc2[r][cp], a2[cp], sTA2);
                if (row < colBase + 2*cp)     sSP += 2.f * softplusf(t0);
                if (row < colBase + 2*cp + 1) sSP += 2.f * softplusf(t1);
            }
        }
    }
    {
        float t0, t1;
        UPK2(t0, t1, sTA2);
        sTA += t0 + t1;
    }

    // ---- deterministic reduction ----
#pragma unroll
    for (int o = 16; o > 0; o >>= 1) {
        sSP += __shfl_xor_sync(0xffffffffu, sSP, o);
        sTA += __shfl_xor_sync(0xffffffffu, sTA, o);
    }
    int wid = tid >> 5, lane = tid & 31;
    if (lane == 0) { red[wid] = sSP; red[8 + wid] = sTA; }
    __syncthreads();
    if (tid == 0) {
        float s1 = 0.f, s2 = 0.f;
#pragma unroll
        for (int w = 0; w < 8; w++) { s1 += red[w]; s2 += red[8 + w]; }
        d_partSP[bid] = (double)s1;
        d_partTA[bid] = (double)s2;
    }
}

// ---------- deterministic final reduction ----------
__global__ void k_final(float* __restrict__ out) {
    __shared__ double rSP[256], rTA[256];
    int t = threadIdx.x;
    double s1 = 0.0, s2 = 0.0;
    for (int i = t; i < NBLK; i += 256) { s1 += d_partSP[i]; s2 += d_partTA[i]; }
    rSP[t] = s1; rTA[t] = s2; __syncthreads();
    for (int s = 128; s > 0; s >>= 1) {
        if (t < s) { rSP[t] += rSP[t+s]; rTA[t] += rTA[t+s]; }
        __syncthreads();
    }
    if (t == 0) out[0] = (float)(0.5 * rTA[0] - 0.5 * rSP[0]);
}

extern "C" void kernel_launch(void* const* d_in, const int* in_sizes, int n_in,
                              void* d_out, int out_size) {
    const float* A    = (const float*)d_in[0];
    const float* beta = (const float*)d_in[1];
    const float* a    = (const float*)d_in[2];
    const float* X    = (const float*)d_in[3];
    const float* C    = (const float*)d_in[4];
    float* out = (float*)d_out;

    cudaFuncSetAttribute(k_pairs, cudaFuncAttributeMaxDynamicSharedMemorySize, OFF_SMEM2);

    k_prep<<<PB, 512>>>(X, C);                       // 1 (rebuilt: 512 threads)
    k_wredM<<<1, 256>>>();                           // 2
    k_ya<<<NN/32, 256>>>(X, beta, a);                // 3
    k_pairs<<<NBLK, 256, OFF_SMEM2>>>(X, A);         // 4  <- profiled slot
    k_final<<<1, 256>>>(out);                        // 5
}